// round 3
// baseline (speedup 1.0000x reference)
#include <cuda_runtime.h>
#include <math.h>

#define Bc 2
#define Mc 8192
#define Nc (Bc * Mc)
#define KF 16
#define KN 8
#define NB 4096          // rank buckets per cloud
#define BCAP 64

#define SLICES 4
#define SLICE_LEN (Mc / SLICES)      // 2048
#define QPB 512                      // queries per knn block (= threads)
#define CHUNKS (Mc / QPB)            // 16 per cloud
#define KNN_BLOCKS (Bc * CHUNKS * SLICES)  // 128

// ---- scratch (device globals; no allocation allowed) ----
__device__ float  g_pd[(size_t)Nc * SLICES * KF];
__device__ int    g_pi[(size_t)Nc * SLICES * KF];
__device__ int    g_knn[(size_t)Nc * KF];
__device__ double g_acc[8];
__device__ int    g_hist[Bc][NB];
__device__ int    g_pref[Bc][NB];
__device__ int    g_members[Bc][NB * BCAP];

// sorted ascending insertion into 16-entry (d,i) list; strict < keeps
// earlier index on ties (matches jax top_k tie-breaking with scan order)
__device__ __forceinline__ void insert16(float v, int vi, float dd[KF], int ii[KF]) {
#pragma unroll
    for (int t = 0; t < KF; ++t) {
        bool lt = (v < dd[t]);
        float tv = lt ? dd[t] : v;
        int   ti = lt ? ii[t] : vi;
        dd[t] = lt ? v : dd[t];
        ii[t] = lt ? vi : ii[t];
        v = tv; vi = ti;
    }
}

// ================= kNN: thread-per-query, deferred hit buffer =================
extern "C" __global__ void __launch_bounds__(QPB, 1)
knn_kernel(const float* __restrict__ coords) {
    __shared__ float4 sh[SLICE_LEN];   // 32KB: this block's candidate slice

    const int tid = threadIdx.x;
    const int cloud = blockIdx.x / (CHUNKS * SLICES);
    const int rem   = blockIdx.x % (CHUNKS * SLICES);
    const int chunk = rem / SLICES;
    const int sl    = rem % SLICES;
    const int slbase = sl * SLICE_LEN;

    const float* cb = coords + (size_t)cloud * Mc * 3;
    for (int i = tid; i < SLICE_LEN; i += QPB) {
        const int jg = slbase + i;
        float x = cb[3 * jg], y = cb[3 * jg + 1], z = cb[3 * jg + 2];
        sh[i] = make_float4(x, y, z, fmaf(x, x, fmaf(y, y, z * z)));
    }
    __syncthreads();

    const int qloc = chunk * QPB + tid;
    const float qx = -2.0f * cb[3 * qloc];
    const float qy = -2.0f * cb[3 * qloc + 1];
    const float qz = -2.0f * cb[3 * qloc + 2];

    float dd[KF]; int ii[KF];
#pragma unroll
    for (int t = 0; t < KF; ++t) { dd[t] = 3.4e38f; ii[t] = 0x7fffffff; }

    // seed: first 16 candidates, unconditional warp-synchronous inserts
#pragma unroll
    for (int j = 0; j < KF; ++j) {
        float4 c = sh[j];
        float d = fmaf(qx, c.x, fmaf(qy, c.y, fmaf(qz, c.z, c.w)));
        insert16(d, slbase + j, dd, ii);
    }

    float bd[8]; int bi[8];   // per-lane pending-hit buffer (local mem ok)
    int pend = 0;

#define KNN_BODY(J)                                                         \
    {                                                                       \
        float4 c = sh[(J)];                                                 \
        float d = fmaf(qx, c.x, fmaf(qy, c.y, fmaf(qz, c.z, c.w)));         \
        if (d < dd[KF - 1]) {                                               \
            if (pend == 8) {                                                \
                _Pragma("unroll 1")                                         \
                for (int k = 0; k < 8; ++k)                                 \
                    if (bd[k] < dd[KF - 1]) insert16(bd[k], bi[k], dd, ii); \
                pend = 0;                                                   \
            }                                                               \
            bd[pend] = d; bi[pend] = slbase + (J); ++pend;                  \
        }                                                                   \
    }

#define KNN_DRAIN()                                                         \
    {                                                                       \
        if (pend) {                                                         \
            _Pragma("unroll 1")                                             \
            for (int k = 0; k < pend; ++k)                                  \
                if (bd[k] < dd[KF - 1]) insert16(bd[k], bi[k], dd, ii);     \
            pend = 0;                                                       \
        }                                                                   \
    }

    // first partial window [16,128)
#pragma unroll 16
    for (int j = KF; j < 128; ++j) KNN_BODY(j);
    KNN_DRAIN();
    // 15 full windows of 128
#pragma unroll 1
    for (int w = 1; w < SLICE_LEN / 128; ++w) {
        const int b0 = w << 7;
#pragma unroll 16
        for (int j = b0; j < b0 + 128; ++j) KNN_BODY(j);
        KNN_DRAIN();
    }

    // write sorted partial result
    float* od = g_pd + ((size_t)(cloud * Mc + qloc) * SLICES + sl) * KF;
    int*   oi = g_pi + ((size_t)(cloud * Mc + qloc) * SLICES + sl) * KF;
#pragma unroll
    for (int t = 0; t < KF; ++t) { od[t] = dd[t]; oi[t] = ii[t]; }
}

// ================= merge 4 sorted partials -> global top-16 =================
#define MQPB 64
__global__ void __launch_bounds__(MQPB, 8) merge_kernel() {
    __shared__ float smd[MQPB * 65];
    __shared__ int   smi[MQPB * 65];
    const int tid = threadIdx.x;
    const size_t qbase = (size_t)blockIdx.x * MQPB;

    for (int k = tid; k < MQPB * 64; k += MQPB) {
        const int qq = k >> 6, o = k & 63;
        smd[qq * 65 + o] = g_pd[(qbase + qq) * 64 + o];
        smi[qq * 65 + o] = g_pi[(qbase + qq) * 64 + o];
    }
    __syncthreads();

    const int q = (int)qbase + tid;
    const int goff = (q >> 13) << 13;
    const float* ld = &smd[tid * 65];
    const int*   li = &smi[tid * 65];
    int p0 = 0, p1 = 0, p2 = 0, p3 = 0;
    int* out = g_knn + (size_t)q * KF;
#pragma unroll 1
    for (int r = 0; r < KF; ++r) {
        float d0 = ld[p0];      int i0 = li[p0];
        float d1 = ld[16 + p1]; int i1 = li[16 + p1];
        float d2 = ld[32 + p2]; int i2 = li[32 + p2];
        float d3 = ld[48 + p3]; int i3 = li[48 + p3];
        float da; int ia; int la;
        if (d1 < d0 || (d1 == d0 && i1 < i0)) { da = d1; ia = i1; la = 1; }
        else                                  { da = d0; ia = i0; la = 0; }
        float db; int ib; int lb;
        if (d3 < d2 || (d3 == d2 && i3 < i2)) { db = d3; ib = i3; lb = 3; }
        else                                  { db = d2; ib = i2; lb = 2; }
        int sel; int bi_;
        if (db < da || (db == da && ib < ia)) { sel = lb; bi_ = ib; }
        else                                  { sel = la; bi_ = ia; }
        out[r] = goff + bi_;
        if      (sel == 0) ++p0;
        else if (sel == 1) ++p1;
        else if (sel == 2) ++p2;
        else               ++p3;
    }
}

// ================= rank bucketing (exact, replaces sort) =================
__global__ void zero_kernel() {
    const int t = blockIdx.x * blockDim.x + threadIdx.x;
    if (t < 8) g_acc[t] = 0.0;
    for (int i = t; i < Bc * NB; i += gridDim.x * blockDim.x)
        ((int*)g_hist)[i] = 0;
}

__global__ void rank_build_kernel(const float* __restrict__ scores) {
    const int i = blockIdx.x * blockDim.x + threadIdx.x;
    if (i >= Nc) return;
    const int cloud = i >> 13;
    const int local = i & (Mc - 1);
    const float s = scores[i];
    int b = (int)(s * (float)NB);
    b = b < 0 ? 0 : (b > NB - 1 ? NB - 1 : b);
    const int slot = atomicAdd(&g_hist[cloud][b], 1);
    if (slot < BCAP) g_members[cloud][b * BCAP + slot] = local;
}

__global__ void prefix_kernel() {
    __shared__ int sc[1024];
    const int cloud = blockIdx.x;
    const int t = threadIdx.x;
    const int base = t * 4;
    int h0 = g_hist[cloud][base + 0];
    int h1 = g_hist[cloud][base + 1];
    int h2 = g_hist[cloud][base + 2];
    int h3 = g_hist[cloud][base + 3];
    int sum = h0 + h1 + h2 + h3;
    sc[t] = sum;
    __syncthreads();
    for (int off = 1; off < 1024; off <<= 1) {
        int v = (t >= off) ? sc[t - off] : 0;
        __syncthreads();
        sc[t] += v;
        __syncthreads();
    }
    int excl = sc[t] - sum;
    g_pref[cloud][base + 0] = excl; excl += h0;
    g_pref[cloud][base + 1] = excl; excl += h1;
    g_pref[cloud][base + 2] = excl; excl += h2;
    g_pref[cloud][base + 3] = excl;
}

// ================= per-point losses (+ rank dist loss) =================
__global__ void loss_points_kernel(const float* __restrict__ scores,
                                   const float* __restrict__ coords) {
    const int i = blockIdx.x * blockDim.x + threadIdx.x;
    double acc[6] = {0, 0, 0, 0, 0, 0};

    {
        const float si = scores[i];
        const float xi = coords[3 * i], yi = coords[3 * i + 1], zi = coords[3 * i + 2];
        float nsum = 0.0f;
        const int* nb = g_knn + (size_t)i * KF;
#pragma unroll
        for (int r = 0; r < KF; ++r) {
            const int n = nb[r];
            const float sn = scores[n];
            const float sd = fabsf(si - sn);
            const float x = (1.0f - sd) * 2.0f;
            const float sig = 1.0f / (1.0f + expf(-x));
            if (r < KN) {
                const float dx = xi - coords[3 * n];
                const float dy = yi - coords[3 * n + 1];
                const float dz = zi - coords[3 * n + 2];
                const float dist = sqrtf(dx * dx + dy * dy + dz * dz);
                const float w = expf(-dist * 10.0f);
                acc[0] += (double)(w * sd * sd);
                acc[1] += (double)w;
                acc[2] += (double)logf(sig + 1e-8f);
                nsum += sn;
            } else {
                acc[3] += (double)logf(1.0f - sig + 1e-8f);
            }
        }
        const float dm = si - nsum * 0.125f;
        acc[4] = (double)(dm * dm);

        const int cloud = i >> 13;
        const int local = i & (Mc - 1);
        int b = (int)(si * (float)NB);
        b = b < 0 ? 0 : (b > NB - 1 ? NB - 1 : b);
        int cnt = g_hist[cloud][b];
        cnt = cnt > BCAP ? BCAP : cnt;
        int r = 0;
        const int* mem = &g_members[cloud][b * BCAP];
        for (int k = 0; k < cnt; ++k) {
            const int m = mem[k];
            const float sm = scores[(cloud << 13) + m];
            r += (sm < si) || (sm == si && m < local);
        }
        const int rank = g_pref[cloud][b] + r;
        const float df = si - (float)rank * (1.0f / (float)(Mc - 1));
        acc[5] = (double)(df * df);
    }

    const int lane = threadIdx.x & 31;
    const int wid = threadIdx.x >> 5;
#pragma unroll
    for (int k = 0; k < 6; ++k)
#pragma unroll
        for (int o = 16; o; o >>= 1)
            acc[k] += __shfl_down_sync(0xffffffffu, acc[k], o);

    __shared__ double red[8][6];
    if (lane == 0)
#pragma unroll
        for (int k = 0; k < 6; ++k) red[wid][k] = acc[k];
    __syncthreads();
    if (wid == 0 && lane < 6) {
        double s = 0.0;
#pragma unroll
        for (int w = 0; w < 8; ++w) s += red[w][lane];
        atomicAdd(&g_acc[lane], s);
    }
}

// ================= finalize =================
__global__ void finalize_kernel(float* out) {
    const double l_loc = g_acc[0] / fmax(g_acc[1], 1e-8);
    const double l_pos = -g_acc[2] / (double)((size_t)Nc * KN);
    const double l_neg = -g_acc[3] / (double)((size_t)Nc * KN);
    const double l_con = l_pos + l_neg;
    const double l_smooth = g_acc[4] / (double)Nc;
    const double l_dist = g_acc[5] / (double)Nc;
    out[0] = (float)(1.0 * l_loc + 0.5 * l_con + 0.3 * l_dist + 0.2 * l_smooth);
}

extern "C" void kernel_launch(void* const* d_in, const int* in_sizes, int n_in,
                              void* d_out, int out_size) {
    const float* scores = (const float*)d_in[0];
    const float* coords = (const float*)d_in[1];
    (void)in_sizes; (void)n_in; (void)out_size;

    zero_kernel<<<16, 1024>>>();
    rank_build_kernel<<<Nc / 256, 256>>>(scores);
    prefix_kernel<<<Bc, 1024>>>();
    knn_kernel<<<KNN_BLOCKS, QPB>>>(coords);
    merge_kernel<<<Nc / MQPB, MQPB>>>();
    loss_points_kernel<<<Nc / 256, 256>>>(scores, coords);
    finalize_kernel<<<1, 1>>>((float*)d_out);
}

// round 4
// speedup vs baseline: 2.2447x; 2.2447x over previous
#include <cuda_runtime.h>
#include <math.h>

#define Bc 2
#define Mc 8192
#define Nc (Bc * Mc)
#define KF 16
#define KN 8
#define NB 4096
#define BCAP 64

#define QPB 128                 // queries per block
#define SPLITS 4                // slice-threads per query
#define KTH (QPB * SPLITS)      // 512 threads
#define SLICE (Mc / SPLITS)     // 2048 candidates per thread
#define QBLKS (Mc / QPB)        // 64 blocks per cloud

// ---- scratch (device globals; no allocation allowed) ----
__device__ int    g_knn[(size_t)Nc * KF];
__device__ double g_acc[8];
__device__ int    g_hist[Bc][NB];
__device__ int    g_pref[Bc][NB];
__device__ int    g_members[Bc][NB * BCAP];

// ----- branch-free compare-exchange on u32 keys (compile-time direction) -----
__device__ __forceinline__ void ce(unsigned& a, unsigned& b, bool up) {
    unsigned lo = min(a, b), hi = max(a, b);
    a = up ? lo : hi;
    b = up ? hi : lo;
}

// bitonic sort 16 keys ascending (fully unrolled; 80 CE)
__device__ __forceinline__ void sort16(unsigned k[16]) {
#pragma unroll
    for (int kk = 2; kk <= 16; kk <<= 1)
#pragma unroll
        for (int j = kk >> 1; j; j >>= 1)
#pragma unroll
            for (int i = 0; i < 16; ++i) {
                int l = i ^ j;
                if (l > i) ce(k[i], k[l], (i & kk) == 0);
            }
}

// clean a bitonic sequence of 16 -> ascending (32 CE)
__device__ __forceinline__ void clean16(unsigned k[16]) {
#pragma unroll
    for (int j = 8; j; j >>= 1)
#pragma unroll
        for (int i = 0; i < 16; ++i) {
            int l = i ^ j;
            if (l > i) ce(k[i], k[l], true);
        }
}

// float -> order-preserving unsigned
__device__ __forceinline__ unsigned sortable(float f) {
    unsigned u = __float_as_uint(f);
    return u ^ (((unsigned)((int)u >> 31)) | 0x80000000u);
}

// ================= kNN: thread-per-query, batch-sort selection =================
extern "C" __global__ void __launch_bounds__(KTH, 1)
knn_kernel(const float* __restrict__ coords) {
    extern __shared__ unsigned char sraw[];
    float4* sh = (float4*)sraw;

    const int tid = threadIdx.x;
    const int cloud = blockIdx.x >> 6;      // 64 qblocks per cloud
    const int qblk = blockIdx.x & 63;

    const float* cb = coords + (size_t)cloud * Mc * 3;
    for (int i = tid; i < Mc; i += KTH) {
        float x = cb[3 * i], y = cb[3 * i + 1], z = cb[3 * i + 2];
        sh[i] = make_float4(x, y, z, fmaf(x, x, fmaf(y, y, z * z)));
    }
    __syncthreads();

    const int qLocal = tid & (QPB - 1);     // lanes of a warp: 32 consecutive queries
    const int split = tid >> 7;             // warp-uniform
    const int q = qblk * QPB + qLocal;
    const int slbase = split * SLICE;

    const float4 qc = sh[q];
    const float qx = -2.0f * qc.x;
    const float qy = -2.0f * qc.y;
    const float qz = -2.0f * qc.z;

    // running top-16 keys, ascending: key = d21<<11 | localIdx(11b)
    unsigned tk[16];
    {
        const float4* p = sh + slbase;
#pragma unroll
        for (int i = 0; i < 16; ++i) {
            float4 c = p[i];
            float d = fmaf(qx, c.x, fmaf(qy, c.y, fmaf(qz, c.z, c.w)));
            tk[i] = (sortable(d) & 0xFFFFF800u) | (unsigned)i;
        }
        sort16(tk);
    }

#pragma unroll 1
    for (int b = 1; b < SLICE / 16; ++b) {
        const int base = b * 16;
        const float4* p = sh + slbase + base;
        unsigned bk[16];
#pragma unroll
        for (int i = 0; i < 16; ++i) {
            float4 c = p[i];
            float d = fmaf(qx, c.x, fmaf(qy, c.y, fmaf(qz, c.z, c.w)));
            bk[i] = (sortable(d) & 0xFFFFF800u) | (unsigned)(base + i);
        }
        sort16(bk);
        // keep 16 smallest of (tk ∪ bk): elementwise min vs reversed, then clean
#pragma unroll
        for (int i = 0; i < 16; ++i) tk[i] = min(tk[i], bk[15 - i]);
        clean16(tk);
    }

    // ---- in-block 4-way merge (exact lexicographic on (d21, gidx)) ----
    __syncthreads();                         // done reading coords
    int* sd = (int*)sraw;                    // [QPB*65] distances (21-bit)
    int* sg = sd + QPB * 65;                 // [QPB*65] global-local indices
    const int rowbase = qLocal * 65 + split * 16;
#pragma unroll
    for (int t = 0; t < 16; ++t) {
        unsigned key = tk[t];
        sd[rowbase + t] = (int)(key >> 11);
        sg[rowbase + t] = slbase + (int)(key & 0x7FFu);
    }
    __syncthreads();

    if (split == 0) {
        const int* ld = sd + qLocal * 65;
        const int* lg = sg + qLocal * 65;
        const int goff = cloud * Mc;
        int p0 = 0, p1 = 0, p2 = 0, p3 = 0;
        int* out = g_knn + ((size_t)goff + q) * KF;
#pragma unroll 1
        for (int r = 0; r < KF; ++r) {
            int d0 = ld[p0];      int g0 = lg[p0];
            int d1 = ld[16 + p1]; int g1 = lg[16 + p1];
            int d2 = ld[32 + p2]; int g2 = lg[32 + p2];
            int d3 = ld[48 + p3]; int g3 = lg[48 + p3];
            int da, ga, la;
            if (d1 < d0 || (d1 == d0 && g1 < g0)) { da = d1; ga = g1; la = 1; }
            else                                  { da = d0; ga = g0; la = 0; }
            int db, gb, lb;
            if (d3 < d2 || (d3 == d2 && g3 < g2)) { db = d3; gb = g3; lb = 3; }
            else                                  { db = d2; gb = g2; lb = 2; }
            int sel, gbest;
            if (db < da || (db == da && gb < ga)) { sel = lb; gbest = gb; }
            else                                  { sel = la; gbest = ga; }
            out[r] = goff + gbest;
            if      (sel == 0) ++p0;
            else if (sel == 1) ++p1;
            else if (sel == 2) ++p2;
            else               ++p3;
        }
    }
}

// ================= rank bucketing (exact, replaces sort) =================
__global__ void zero_kernel() {
    const int t = blockIdx.x * blockDim.x + threadIdx.x;
    if (t < 8) g_acc[t] = 0.0;
    for (int i = t; i < Bc * NB; i += gridDim.x * blockDim.x)
        ((int*)g_hist)[i] = 0;
}

__global__ void rank_build_kernel(const float* __restrict__ scores) {
    const int i = blockIdx.x * blockDim.x + threadIdx.x;
    if (i >= Nc) return;
    const int cloud = i >> 13;
    const int local = i & (Mc - 1);
    const float s = scores[i];
    int b = (int)(s * (float)NB);
    b = b < 0 ? 0 : (b > NB - 1 ? NB - 1 : b);
    const int slot = atomicAdd(&g_hist[cloud][b], 1);
    if (slot < BCAP) g_members[cloud][b * BCAP + slot] = local;
}

__global__ void prefix_kernel() {
    __shared__ int sc[1024];
    const int cloud = blockIdx.x;
    const int t = threadIdx.x;
    const int base = t * 4;
    int h0 = g_hist[cloud][base + 0];
    int h1 = g_hist[cloud][base + 1];
    int h2 = g_hist[cloud][base + 2];
    int h3 = g_hist[cloud][base + 3];
    int sum = h0 + h1 + h2 + h3;
    sc[t] = sum;
    __syncthreads();
    for (int off = 1; off < 1024; off <<= 1) {
        int v = (t >= off) ? sc[t - off] : 0;
        __syncthreads();
        sc[t] += v;
        __syncthreads();
    }
    int excl = sc[t] - sum;
    g_pref[cloud][base + 0] = excl; excl += h0;
    g_pref[cloud][base + 1] = excl; excl += h1;
    g_pref[cloud][base + 2] = excl; excl += h2;
    g_pref[cloud][base + 3] = excl;
}

// ================= per-point losses (+ rank dist loss) =================
__global__ void loss_points_kernel(const float* __restrict__ scores,
                                   const float* __restrict__ coords) {
    const int i = blockIdx.x * blockDim.x + threadIdx.x;
    double acc[6] = {0, 0, 0, 0, 0, 0};

    {
        const float si = scores[i];
        const float xi = coords[3 * i], yi = coords[3 * i + 1], zi = coords[3 * i + 2];
        float nsum = 0.0f;
        const int* nb = g_knn + (size_t)i * KF;
#pragma unroll
        for (int r = 0; r < KF; ++r) {
            const int n = nb[r];
            const float sn = scores[n];
            const float sd = fabsf(si - sn);
            const float x = (1.0f - sd) * 2.0f;
            const float sig = 1.0f / (1.0f + expf(-x));
            if (r < KN) {
                const float dx = xi - coords[3 * n];
                const float dy = yi - coords[3 * n + 1];
                const float dz = zi - coords[3 * n + 2];
                const float dist = sqrtf(dx * dx + dy * dy + dz * dz);
                const float w = expf(-dist * 10.0f);
                acc[0] += (double)(w * sd * sd);
                acc[1] += (double)w;
                acc[2] += (double)logf(sig + 1e-8f);
                nsum += sn;
            } else {
                acc[3] += (double)logf(1.0f - sig + 1e-8f);
            }
        }
        const float dm = si - nsum * 0.125f;
        acc[4] = (double)(dm * dm);

        const int cloud = i >> 13;
        const int local = i & (Mc - 1);
        int b = (int)(si * (float)NB);
        b = b < 0 ? 0 : (b > NB - 1 ? NB - 1 : b);
        int cnt = g_hist[cloud][b];
        cnt = cnt > BCAP ? BCAP : cnt;
        int r = 0;
        const int* mem = &g_members[cloud][b * BCAP];
        for (int k = 0; k < cnt; ++k) {
            const int m = mem[k];
            const float sm = scores[(cloud << 13) + m];
            r += (sm < si) || (sm == si && m < local);
        }
        const int rank = g_pref[cloud][b] + r;
        const float df = si - (float)rank * (1.0f / (float)(Mc - 1));
        acc[5] = (double)(df * df);
    }

    const int lane = threadIdx.x & 31;
    const int wid = threadIdx.x >> 5;
#pragma unroll
    for (int k = 0; k < 6; ++k)
#pragma unroll
        for (int o = 16; o; o >>= 1)
            acc[k] += __shfl_down_sync(0xffffffffu, acc[k], o);

    __shared__ double red[8][6];
    if (lane == 0)
#pragma unroll
        for (int k = 0; k < 6; ++k) red[wid][k] = acc[k];
    __syncthreads();
    if (wid == 0 && lane < 6) {
        double s = 0.0;
#pragma unroll
        for (int w = 0; w < 8; ++w) s += red[w][lane];
        atomicAdd(&g_acc[lane], s);
    }
}

// ================= finalize =================
__global__ void finalize_kernel(float* out) {
    const double l_loc = g_acc[0] / fmax(g_acc[1], 1e-8);
    const double l_pos = -g_acc[2] / (double)((size_t)Nc * KN);
    const double l_neg = -g_acc[3] / (double)((size_t)Nc * KN);
    const double l_con = l_pos + l_neg;
    const double l_smooth = g_acc[4] / (double)Nc;
    const double l_dist = g_acc[5] / (double)Nc;
    out[0] = (float)(1.0 * l_loc + 0.5 * l_con + 0.3 * l_dist + 0.2 * l_smooth);
}

extern "C" void kernel_launch(void* const* d_in, const int* in_sizes, int n_in,
                              void* d_out, int out_size) {
    const float* scores = (const float*)d_in[0];
    const float* coords = (const float*)d_in[1];
    (void)in_sizes; (void)n_in; (void)out_size;

    cudaFuncSetAttribute(knn_kernel,
                         cudaFuncAttributeMaxDynamicSharedMemorySize,
                         Mc * (int)sizeof(float4));

    zero_kernel<<<16, 1024>>>();
    rank_build_kernel<<<Nc / 256, 256>>>(scores);
    prefix_kernel<<<Bc, 1024>>>();
    knn_kernel<<<Bc * QBLKS, KTH, Mc * sizeof(float4)>>>(coords);
    loss_points_kernel<<<Nc / 256, 256>>>(scores, coords);
    finalize_kernel<<<1, 1>>>((float*)d_out);
}